// round 14
// baseline (speedup 1.0000x reference)
#include <cuda_runtime.h>

#define NN 16000
#define KNN 16
#define FIN 32
#define HID 64
#define G 64
#define NCELL (G * G)
#define CAP 32            // max points per cell (lambda ~3.9)
#define QPB 8             // queries (=warps) per block
#define SLOTCAP 256       // per-warp candidate table (T ~97 typical)
#define FSLOTCAP 768      // fallback 9x9 window table (T ~320 typical)
#define FBWARPS 512       // fallback: 64 blocks x 8 warps
#define FULLM 0xFFFFFFFFu

// ---------------- scratch (device globals; no allocation allowed) ----------
__device__ float4 g_pts[NN];              // {x, y, x^2+y^2, id-bits}
__device__ float4 g_binpts[NCELL * CAP];  // packed candidates per cell
__device__ int    g_bcnt[NCELL];          // per-cell fill counts
__device__ int    g_fbn;                  // # flagged queries
__device__ int    g_fbq[NN];              // compacted flagged query list
__device__ int    g_knn[NN * KNN];        // neighbor (src) indices (sorted)
__device__ float  g_d  [NN * KNN];        // edge distances
__device__ float  g_ew [NN * KNN];        // normalized inverted distances
__device__ float  g_dis[NN];              // deg^{-1/2}
__device__ unsigned g_minmax[2];          // [0]=min bits, [1]=max bits (d>=0)
__device__ unsigned g_bbox[4];            // ordered-uint minx,maxx,miny,maxy
__device__ float  g_bufA[NN * HID];       // x@W1
__device__ float  g_bufB[NN * HID];       // h1@W2

// 5x5 window offsets in center-out ring order (tightens cmax early)
__constant__ signed char WDX[25] = {0, -1,0,1,-1,1,-1,0,1,
                                    -2,-1,0,1,2, -2,2, -2,2, -2,2, -2,-1,0,1,2};
__constant__ signed char WDY[25] = {0, -1,-1,-1,0,0,1,1,1,
                                    -2,-2,-2,-2,-2, -1,-1, 0,0, 1,1, 2,2,2,2,2};

// ordered-uint map: monotone with float order (handles negatives)
__device__ __forceinline__ unsigned enc_ord(float f) {
    unsigned b = __float_as_uint(f);
    return (b & 0x80000000u) ? ~b : (b | 0x80000000u);
}
__device__ __forceinline__ float dec_ord(unsigned u) {
    return (u & 0x80000000u) ? __uint_as_float(u & 0x7FFFFFFFu)
                             : __uint_as_float(~u);
}

struct Grid { float minx, miny, invsx, invsy, smin; };
__device__ __forceinline__ Grid load_grid() {
    Grid g;
    g.minx = dec_ord(g_bbox[0]);
    float maxx = dec_ord(g_bbox[1]);
    g.miny = dec_ord(g_bbox[2]);
    float maxy = dec_ord(g_bbox[3]);
    float wx = fmaxf(maxx - g.minx, 1e-20f);
    float wy = fmaxf(maxy - g.miny, 1e-20f);
    g.invsx = (float)G / wx;
    g.invsy = (float)G / wy;
    g.smin  = fminf(wx, wy) / (float)G;
    return g;
}
__device__ __forceinline__ int cell_x(const Grid& g, float x) {
    int c = (int)((x - g.minx) * g.invsx);
    return min(max(c, 0), G - 1);
}
__device__ __forceinline__ int cell_y(const Grid& g, float y) {
    int c = (int)((y - g.miny) * g.invsy);
    return min(max(c, 0), G - 1);
}

// u64 shfl_xor helper
__device__ __forceinline__ unsigned long long shflx64(unsigned long long v,
                                                      int m) {
    unsigned lo = (unsigned)v, hi = (unsigned)(v >> 32);
    lo = __shfl_xor_sync(FULLM, lo, m);
    hi = __shfl_xor_sync(FULLM, hi, m);
    return ((unsigned long long)hi << 32) | lo;
}

// bit-exact d2 key vs query 'me'/'q' (shared by all paths)
__device__ __forceinline__ unsigned long long cand_key(const float4& me, int q,
                                                       const float4& pt) {
    int j = __float_as_int(pt.w);
    float dot = __fmaf_rn(me.y, pt.y, __fmul_rn(me.x, pt.x));
    float d2  = __fsub_rn(__fadd_rn(me.z, pt.z), __fmul_rn(2.0f, dot));
    unsigned long long key =
        ((unsigned long long)enc_ord(d2) << 32) | (unsigned)j;
    return (j == q) ? ~0ULL : key;
}

// warp bitonic round-0 + pipelined ballot-insert over slot table.
// Returns sorted min-16 in lanes 0..15 (lkey) and cmax (=lane15 key).
__device__ __forceinline__ void warp_topk(const float4& me, int q, int lane,
                                          const int* saddr, int T,
                                          unsigned long long& lkey,
                                          unsigned long long& cmax) {
    unsigned long long mykey = ~0ULL;
    if (lane < T) mykey = cand_key(me, q, g_binpts[saddr[lane]]);
#pragma unroll
    for (int k = 2; k <= 32; k <<= 1) {
#pragma unroll
        for (int jj = k >> 1; jj > 0; jj >>= 1) {
            unsigned long long other = shflx64(mykey, jj);
            bool tmin = (((lane & jj) == 0) == ((lane & k) == 0));
            mykey = tmin ? min(mykey, other) : max(mykey, other);
        }
    }
    lkey = mykey;
    cmax = __shfl_sync(FULLM, lkey, 15);

    const int R = (T + 31) >> 5;
    for (int rb = 1; rb < R; rb += 4) {
        unsigned long long mk[4];
#pragma unroll
        for (int u = 0; u < 4; u++) {
            mk[u] = ~0ULL;
            int f = (rb + u) * 32 + lane;
            if (rb + u < R && f < T)
                mk[u] = cand_key(me, q, g_binpts[saddr[f]]);
        }
#pragma unroll
        for (int u = 0; u < 4; u++) {
            bool pend = (mk[u] < cmax);
            unsigned bal = __ballot_sync(FULLM, pend);
            while (bal) {
                int src = __ffs((int)bal) - 1;
                unsigned long long K = __shfl_sync(FULLM, mk[u], src);
                unsigned lt = __ballot_sync(FULLM, lkey < K) & 0xFFFFu;
                int pos = __popc(lt);
                unsigned long long up = __shfl_up_sync(FULLM, lkey, 1);
                lkey = (lane == pos) ? K : ((lane > pos) ? up : lkey);
                cmax = __shfl_sync(FULLM, lkey, 15);
                pend = pend && (lane != src) && (mk[u] < cmax);
                bal = __ballot_sync(FULLM, pend);
            }
        }
    }
}

// warp epilogue: write knn + distances, reduce minmax, atomics to target
__device__ __forceinline__ void warp_epilogue(const float4& me, int q, int lane,
                                              unsigned long long lkey,
                                              unsigned* mn_t, unsigned* mx_t) {
    unsigned lmn = 0x7F800000u, lmx = 0u;
    if (lane < 16) {
        int j = (int)(lkey & 0xFFFFFFFFULL);
        g_knn[q * KNN + lane] = j;
        float4 nb = g_pts[j];
        float dx = __fsub_rn(me.x, nb.x);
        float dy = __fsub_rn(me.y, nb.y);
        float d  = __fsqrt_rn(__fadd_rn(__fmul_rn(dx, dx),
                                        __fmul_rn(dy, dy)));
        g_d[q * KNN + lane] = d;
        unsigned b = __float_as_uint(d);
        lmn = b; lmx = b;
    }
    lmn = __reduce_min_sync(FULLM, lmn);
    lmx = __reduce_max_sync(FULLM, lmx);
    if (lane == 0) { atomicMin(mn_t, lmn); atomicMax(mx_t, lmx); }
}

// ---------------- K1: init + pack + bbox (block-reduced atomics) ------------
__global__ void prep_kernel(const float* __restrict__ c) {
    __shared__ unsigned red[4][8];
    int i = blockIdx.x * 256 + threadIdx.x;
    if (i < NCELL) g_bcnt[i] = 0;
    if (i == 0) { g_minmax[0] = 0x7F800000u; g_minmax[1] = 0u;
                  g_fbn = 0;
                  g_bbox[0] = 0xFFFFFFFFu; g_bbox[1] = 0u;
                  g_bbox[2] = 0xFFFFFFFFu; g_bbox[3] = 0u; }
    unsigned exn = 0xFFFFFFFFu, exx = 0u, eyn = 0xFFFFFFFFu, eyx = 0u;
    if (i < NN) {
        float x = c[2 * i], y = c[2 * i + 1];
        float sq = __fadd_rn(__fmul_rn(x, x), __fmul_rn(y, y));
        g_pts[i] = make_float4(x, y, sq, __int_as_float(i));
        unsigned ex = enc_ord(x), ey = enc_ord(y);
        exn = ex; exx = ex; eyn = ey; eyx = ey;
    }
    exn = __reduce_min_sync(FULLM, exn);
    exx = __reduce_max_sync(FULLM, exx);
    eyn = __reduce_min_sync(FULLM, eyn);
    eyx = __reduce_max_sync(FULLM, eyx);
    int w = threadIdx.x >> 5;
    if ((threadIdx.x & 31) == 0) {
        red[0][w] = exn; red[1][w] = exx; red[2][w] = eyn; red[3][w] = eyx;
    }
    __syncthreads();
    if (threadIdx.x < 4) {
        unsigned v = red[threadIdx.x][0];
        bool ismin = (threadIdx.x & 1) == 0;
#pragma unroll
        for (int k = 1; k < 8; k++)
            v = ismin ? min(v, red[threadIdx.x][k]) : max(v, red[threadIdx.x][k]);
        if (ismin) atomicMin(&g_bbox[threadIdx.x], v);
        else       atomicMax(&g_bbox[threadIdx.x], v);
    }
}

// ---------------- K2: bin fill (blocks < NBF) + x@W1 (rest) -----------------
#define NBF 63
__global__ void fill_mm1_kernel(const float* __restrict__ x,
                                const float* __restrict__ W1) {
    if (blockIdx.x < NBF) {
        int i = blockIdx.x * 256 + threadIdx.x;
        if (i >= NN) return;
        Grid g = load_grid();
        float4 p = g_pts[i];
        int cell = cell_y(g, p.y) * G + cell_x(g, p.x);
        int slot = atomicAdd(&g_bcnt[cell], 1);
        if (slot < CAP) g_binpts[cell * CAP + slot] = p;
        return;
    }
    __shared__ float sw[FIN * 64];
    int tid = threadIdx.x;
    for (int i = tid; i < FIN * 64; i += 256) sw[i] = W1[i];
    __syncthreads();
    int n = (blockIdx.x - NBF) * 4 + (tid >> 6);
    int f = tid & 63;
    const float* xr = x + n * FIN;
    float acc = 0.0f;
#pragma unroll
    for (int k = 0; k < FIN; k++) acc = fmaf(xr[k], sw[k * 64 + f], acc);
    g_bufA[n * 64 + f] = acc;
}

// ---------------- K3: warp-per-query exact KNN + edges (5x5 window) ---------
__global__ void __launch_bounds__(256, 5) knn_edge_kernel() {
    __shared__ int saddr[QPB][SLOTCAP];
    __shared__ unsigned smn, smx;
    const int lane = threadIdx.x & 31;
    const int w = threadIdx.x >> 5;
    if (threadIdx.x == 0) { smn = 0x7F800000u; smx = 0u; }
    __syncthreads();

    const int q = blockIdx.x * QPB + w;
    const Grid g = load_grid();
    const float4 me = g_pts[q];
    const int cx = cell_x(g, me.x);
    const int cy = cell_y(g, me.y);

    int cnt = 0, cbase = 0;
    if (lane < 25) {
        int gx = cx + WDX[lane], gy = cy + WDY[lane];
        if (gx >= 0 && gx < G && gy >= 0 && gy < G) {
            int cid = gy * G + gx;
            cnt = min(g_bcnt[cid], CAP);
            cbase = cid * CAP;
        }
    }
    int pref = cnt;
#pragma unroll
    for (int off = 1; off < 32; off <<= 1) {
        int v = __shfl_up_sync(FULLM, pref, off);
        if (lane >= off) pref += v;
    }
    const int T = __shfl_sync(FULLM, pref, 24);
    bool needfb = (T > SLOTCAP);

    unsigned long long lkey = ~0ULL, cmax = ~0ULL;
    if (!needfb) {
        int excl = pref - cnt;
        for (int k = 0; k < cnt; k++) saddr[w][excl + k] = cbase + k;
        __syncwarp();
        warp_topk(me, q, lane, saddr[w], T, lkey, cmax);
        // certificate: outside 5x5 window -> d2 >= (2*smin)^2
        float t16 = dec_ord((unsigned)(cmax >> 32));      // NaN if sentinel
        float bside = __fmul_rn(2.0f, g.smin);
        needfb = !(t16 + 1e-4f < __fmul_rn(bside, bside)); // NaN -> fb
    }

    if (!needfb) {
        warp_epilogue(me, q, lane, lkey, &smn, &smx);
    } else if (lane == 0) {
        int pos = atomicAdd(&g_fbn, 1);   // compacted work list
        g_fbq[pos] = q;
    }
    __syncthreads();
    if (threadIdx.x == 0) {
        atomicMin(&g_minmax[0], smn);
        atomicMax(&g_minmax[1], smx);
    }
}

// ---------------- K4: compacted 9x9 fallback (dense work list) --------------
// Fixed 512 warps iterate the compacted list -> ~1 query/warp, full chip.
// Margin 4 -> certificate (4*smin)^2. Scalar full ring walk remains as
// lane-0 ultimate guard (certificate/overflow gated, prob ~0).
__global__ void fallback_kernel() {
    __shared__ int saddr[QPB][FSLOTCAP];
    const int lane = threadIdx.x & 31;
    const int w = threadIdx.x >> 5;
    const int gw = blockIdx.x * QPB + w;  // global warp id
    const int nfb = g_fbn;
    const Grid g = load_grid();

    for (int it = gw; it < nfb; it += FBWARPS) {
        const int q = g_fbq[it];
        const float4 me = g_pts[q];
        const int cx = cell_x(g, me.x);
        const int cy = cell_y(g, me.y);

        // 9x9 window counts in 3 chunks + warp scans -> slot table
        int total = 0;
        bool over = false;
#pragma unroll
        for (int ch = 0; ch < 3; ch++) {
            int idx = ch * 32 + lane;     // 0..95; valid < 81
            int cnt = 0, cbase = 0;
            if (idx < 81) {
                int gx = cx + (idx % 9) - 4, gy = cy + (idx / 9) - 4;
                if (gx >= 0 && gx < G && gy >= 0 && gy < G) {
                    int cid = gy * G + gx;
                    cnt = min(g_bcnt[cid], CAP);
                    cbase = cid * CAP;
                }
            }
            int pref = cnt;
#pragma unroll
            for (int off = 1; off < 32; off <<= 1) {
                int v = __shfl_up_sync(FULLM, pref, off);
                if (lane >= off) pref += v;
            }
            int excl = total + pref - cnt;
            for (int k = 0; k < cnt; k++) {
                if (excl + k < FSLOTCAP) saddr[w][excl + k] = cbase + k;
                else over = true;
            }
            total += __shfl_sync(FULLM, pref, 31);
        }
        over = __any_sync(FULLM, over) || (total > FSLOTCAP);
        __syncwarp();

        unsigned long long lkey = ~0ULL, cmax = ~0ULL;
        bool needscalar = over;
        if (!needscalar) {
            warp_topk(me, q, lane, saddr[w], total, lkey, cmax);
            // certificate: outside 9x9 window -> d2 >= (4*smin)^2
            float t16 = dec_ord((unsigned)(cmax >> 32));
            float bside = __fmul_rn(4.0f, g.smin);
            needscalar = !(t16 + 1e-4f < __fmul_rn(bside, bside));
        }

        if (!needscalar) {
            warp_epilogue(me, q, lane, lkey, &g_minmax[0], &g_minmax[1]);
        } else if (lane == 0) {
            // ultimate guard: exact scalar expanding ring walk
            unsigned long long keys[16];
#pragma unroll
            for (int t = 0; t < 16; t++)
                keys[t] = ~0ULL - (unsigned long long)t;
            unsigned long long cm = ~0ULL;
            for (int r = 0; r < G; r++) {
                if (r >= 2) {
                    float b = (float)(r - 1) * g.smin;
                    float thr = dec_ord((unsigned)(cm >> 32));
                    if (b * b > thr + 1e-4f) break;
                }
                int y0 = cy - r, y1 = cy + r, x0 = cx - r, x1 = cx + r;
                for (int yy = max(y0, 0); yy <= min(y1, G - 1); yy++) {
                    bool erow = (yy == y0) || (yy == y1);
                    int xstep = (erow || r == 0) ? 1 : 2 * r;
                    for (int xx = x0; xx <= x1; xx += xstep) {
                        if (xx < 0 || xx >= G) continue;
                        int cc = yy * G + xx;
                        int c2 = min(g_bcnt[cc], CAP);
                        const float4* bp = &g_binpts[cc * CAP];
                        for (int p = 0; p < c2; p++) {
                            unsigned long long key = cand_key(me, q, bp[p]);
                            if (key < cm) {
                                unsigned long long nm = 0ULL;
#pragma unroll
                                for (int kk = 0; kk < 16; kk++) {
                                    if (keys[kk] == cm) keys[kk] = key;
                                    nm = max(nm, keys[kk]);
                                }
                                cm = nm;
                            }
                        }
                    }
                }
            }
#pragma unroll
            for (int i = 0; i < 15; i++)
#pragma unroll
                for (int t = 0; t < 15 - i; t++)
                    if (keys[t] > keys[t + 1]) {
                        unsigned long long tmp = keys[t];
                        keys[t] = keys[t + 1];
                        keys[t + 1] = tmp;
                    }
            unsigned lmn = 0x7F800000u, lmx = 0u;
#pragma unroll
            for (int t = 0; t < 16; t++) {
                int j = (int)(keys[t] & 0xFFFFFFFFULL);
                g_knn[q * KNN + t] = j;
                float4 nb = g_pts[j];
                float dx = __fsub_rn(me.x, nb.x);
                float dy = __fsub_rn(me.y, nb.y);
                float d  = __fsqrt_rn(__fadd_rn(__fmul_rn(dx, dx),
                                                __fmul_rn(dy, dy)));
                g_d[q * KNN + t] = d;
                unsigned b = __float_as_uint(d);
                lmn = min(lmn, b);
                lmx = max(lmx, b);
            }
            atomicMin(&g_minmax[0], lmn);
            atomicMax(&g_minmax[1], lmx);
        }
    }
}

// ---------------- K5: edge weights + deg^{-1/2} (1 thread / edge) -----------
__global__ void deg_kernel() {
    int e = blockIdx.x * 256 + threadIdx.x;     // coalesced over edges
    float mx  = __uint_as_float(g_minmax[1]);
    float rng = __fsub_rn(mx, __uint_as_float(g_minmax[0]));
    float ew  = __fdiv_rn(__fsub_rn(mx, g_d[e]), rng);
    g_ew[e] = ew;
    float s = ew;
#pragma unroll
    for (int off = 8; off > 0; off >>= 1)
        s += __shfl_down_sync(FULLM, s, off, 16);
    if ((threadIdx.x & 15) == 0)
        g_dis[e >> 4] = rsqrtf(__fadd_rn(1.0f, s));   // +1 self-loop
}

// ---------------- K6: agg1 + relu + h1@W2 (16 nodes x 16 thr, float4) -------
#define ANP 16
__global__ void agg_mm2_kernel(const float* __restrict__ b1,
                               const float* __restrict__ W2) {
    __shared__ float4 sw4[HID * 16];      // W2 as [k][t] float4
    __shared__ float  sh1[ANP][HID];
    const int tid = threadIdx.x;          // 256
    const int r = tid >> 4, t = tid & 15;
    const float4* W24 = (const float4*)W2;
    for (int i = tid; i < HID * 16; i += 256) sw4[i] = W24[i];

    const int n = blockIdx.x * ANP + r;
    const float4* A4 = (const float4*)g_bufA;
    float disn = g_dis[n];
    float dd = __fmul_rn(disn, disn);
    float4 a = A4[n * 16 + t];
    float4 acc;
    acc.x = __fmul_rn(dd, a.x); acc.y = __fmul_rn(dd, a.y);
    acc.z = __fmul_rn(dd, a.z); acc.w = __fmul_rn(dd, a.w);
#pragma unroll
    for (int k = 0; k < KNN; k++) {
        int s = g_knn[n * KNN + k];
        float coef = __fmul_rn(__fmul_rn(g_dis[s], g_ew[n * KNN + k]), disn);
        float4 v = A4[s * 16 + t];
        acc.x = fmaf(coef, v.x, acc.x);
        acc.y = fmaf(coef, v.y, acc.y);
        acc.z = fmaf(coef, v.z, acc.z);
        acc.w = fmaf(coef, v.w, acc.w);
    }
    float4 bb = ((const float4*)b1)[t];
    sh1[r][4 * t + 0] = fmaxf(__fadd_rn(acc.x, bb.x), 0.0f);
    sh1[r][4 * t + 1] = fmaxf(__fadd_rn(acc.y, bb.y), 0.0f);
    sh1[r][4 * t + 2] = fmaxf(__fadd_rn(acc.z, bb.z), 0.0f);
    sh1[r][4 * t + 3] = fmaxf(__fadd_rn(acc.w, bb.w), 0.0f);
    __syncthreads();
    float4 acc2 = make_float4(0.0f, 0.0f, 0.0f, 0.0f);
#pragma unroll
    for (int k = 0; k < HID; k++) {
        float h = sh1[r][k];
        float4 wv = sw4[k * 16 + t];
        acc2.x = fmaf(h, wv.x, acc2.x);
        acc2.y = fmaf(h, wv.y, acc2.y);
        acc2.z = fmaf(h, wv.z, acc2.z);
        acc2.w = fmaf(h, wv.w, acc2.w);
    }
    ((float4*)g_bufB)[n * 16 + t] = acc2;
}

// ---------------- K7: agg2 + relu + FC head (16x16, shfl reduce) ------------
__global__ void final_kernel(const float* __restrict__ b2,
                             const float* __restrict__ wfc,
                             const float* __restrict__ bfc,
                             float* __restrict__ y) {
    const int tid = threadIdx.x;          // 256
    const int r = tid >> 4, t = tid & 15;
    const int n = blockIdx.x * ANP + r;
    const float4* B4 = (const float4*)g_bufB;
    float disn = g_dis[n];
    float dd = __fmul_rn(disn, disn);
    float4 a = B4[n * 16 + t];
    float4 acc;
    acc.x = __fmul_rn(dd, a.x); acc.y = __fmul_rn(dd, a.y);
    acc.z = __fmul_rn(dd, a.z); acc.w = __fmul_rn(dd, a.w);
#pragma unroll
    for (int k = 0; k < KNN; k++) {
        int s = g_knn[n * KNN + k];
        float coef = __fmul_rn(__fmul_rn(g_dis[s], g_ew[n * KNN + k]), disn);
        float4 v = B4[s * 16 + t];
        acc.x = fmaf(coef, v.x, acc.x);
        acc.y = fmaf(coef, v.y, acc.y);
        acc.z = fmaf(coef, v.z, acc.z);
        acc.w = fmaf(coef, v.w, acc.w);
    }
    float4 bb = ((const float4*)b2)[t];
    float4 wv = ((const float4*)wfc)[t];
    float p = 0.0f;
    p = fmaf(fmaxf(__fadd_rn(acc.x, bb.x), 0.0f), wv.x, p);
    p = fmaf(fmaxf(__fadd_rn(acc.y, bb.y), 0.0f), wv.y, p);
    p = fmaf(fmaxf(__fadd_rn(acc.z, bb.z), 0.0f), wv.z, p);
    p = fmaf(fmaxf(__fadd_rn(acc.w, bb.w), 0.0f), wv.w, p);
#pragma unroll
    for (int off = 8; off > 0; off >>= 1)
        p += __shfl_down_sync(FULLM, p, off, 16);
    if (t == 0) y[n] = p + bfc[0];
}

// ---------------- launch -----------------------------------------------------
extern "C" void kernel_launch(void* const* d_in, const int* in_sizes, int n_in,
                              void* d_out, int out_size) {
    const float* x   = (const float*)d_in[0];
    const float* c   = (const float*)d_in[1];
    const float* W1  = (const float*)d_in[2];
    const float* b1  = (const float*)d_in[3];
    const float* W2  = (const float*)d_in[4];
    const float* b2  = (const float*)d_in[5];
    const float* Wfc = (const float*)d_in[6];
    const float* bfc = (const float*)d_in[7];
    float* y = (float*)d_out;

    prep_kernel<<<63, 256>>>(c);                   // 0
    fill_mm1_kernel<<<NBF + NN / 4, 256>>>(x, W1); // 1
    knn_edge_kernel<<<NN / QPB, 256>>>();          // 2
    fallback_kernel<<<FBWARPS / QPB, 256>>>();     // 3 (profiled; dense list)
    deg_kernel<<<NN * KNN / 256, 256>>>();         // 4
    agg_mm2_kernel<<<NN / ANP, 256>>>(b1, W2);     // 5
    final_kernel<<<NN / ANP, 256>>>(b2, Wfc, bfc, y); // 6
}

// round 15
// speedup vs baseline: 1.0612x; 1.0612x over previous
#include <cuda_runtime.h>

#define NN 16000
#define KNN 16
#define FIN 32
#define HID 64
#define G 64
#define NCELL (G * G)
#define CAP 32            // max points per cell (lambda ~3.9)
#define QPB 8             // queries (=warps) per block
#define FSLOTCAP 768      // per-warp slot table (covers 5x5 and 9x9 windows)
#define FULLM 0xFFFFFFFFu

// ---------------- scratch (device globals; no allocation allowed) ----------
__device__ float4 g_pts[NN];              // {x, y, x^2+y^2, id-bits}
__device__ float4 g_binpts[NCELL * CAP];  // packed candidates per cell
__device__ int    g_bcnt[NCELL];          // per-cell fill counts
__device__ int    g_fbn;                  // # scalar-guard queries
__device__ int    g_fbq[NN];              // compacted scalar-guard list
__device__ int    g_knn[NN * KNN];        // neighbor (src) indices (sorted)
__device__ float  g_d  [NN * KNN];        // edge distances
__device__ float  g_ew [NN * KNN];        // normalized inverted distances
__device__ float  g_dis[NN];              // deg^{-1/2}
__device__ unsigned g_minmax[2];          // [0]=min bits, [1]=max bits (d>=0)
__device__ unsigned g_bbox[4];            // ordered-uint minx,maxx,miny,maxy
__device__ float  g_bufA[NN * HID];       // x@W1
__device__ float  g_bufB[NN * HID];       // h1@W2

// 5x5 window offsets in center-out ring order (tightens cmax early)
__constant__ signed char WDX[25] = {0, -1,0,1,-1,1,-1,0,1,
                                    -2,-1,0,1,2, -2,2, -2,2, -2,2, -2,-1,0,1,2};
__constant__ signed char WDY[25] = {0, -1,-1,-1,0,0,1,1,1,
                                    -2,-2,-2,-2,-2, -1,-1, 0,0, 1,1, 2,2,2,2,2};

// ordered-uint map: monotone with float order (handles negatives)
__device__ __forceinline__ unsigned enc_ord(float f) {
    unsigned b = __float_as_uint(f);
    return (b & 0x80000000u) ? ~b : (b | 0x80000000u);
}
__device__ __forceinline__ float dec_ord(unsigned u) {
    return (u & 0x80000000u) ? __uint_as_float(u & 0x7FFFFFFFu)
                             : __uint_as_float(~u);
}

struct Grid { float minx, miny, invsx, invsy, smin; };
__device__ __forceinline__ Grid load_grid() {
    Grid g;
    g.minx = dec_ord(g_bbox[0]);
    float maxx = dec_ord(g_bbox[1]);
    g.miny = dec_ord(g_bbox[2]);
    float maxy = dec_ord(g_bbox[3]);
    float wx = fmaxf(maxx - g.minx, 1e-20f);
    float wy = fmaxf(maxy - g.miny, 1e-20f);
    g.invsx = (float)G / wx;
    g.invsy = (float)G / wy;
    g.smin  = fminf(wx, wy) / (float)G;
    return g;
}
__device__ __forceinline__ int cell_x(const Grid& g, float x) {
    int c = (int)((x - g.minx) * g.invsx);
    return min(max(c, 0), G - 1);
}
__device__ __forceinline__ int cell_y(const Grid& g, float y) {
    int c = (int)((y - g.miny) * g.invsy);
    return min(max(c, 0), G - 1);
}

// u64 shfl_xor helper
__device__ __forceinline__ unsigned long long shflx64(unsigned long long v,
                                                      int m) {
    unsigned lo = (unsigned)v, hi = (unsigned)(v >> 32);
    lo = __shfl_xor_sync(FULLM, lo, m);
    hi = __shfl_xor_sync(FULLM, hi, m);
    return ((unsigned long long)hi << 32) | lo;
}

// bit-exact d2 key vs query 'me'/'q' (shared by all paths)
__device__ __forceinline__ unsigned long long cand_key(const float4& me, int q,
                                                       const float4& pt) {
    int j = __float_as_int(pt.w);
    float dot = __fmaf_rn(me.y, pt.y, __fmul_rn(me.x, pt.x));
    float d2  = __fsub_rn(__fadd_rn(me.z, pt.z), __fmul_rn(2.0f, dot));
    unsigned long long key =
        ((unsigned long long)enc_ord(d2) << 32) | (unsigned)j;
    return (j == q) ? ~0ULL : key;
}

// warp bitonic round-0 + pipelined ballot-insert over slot table.
// Returns sorted min-16 in lanes 0..15 (lkey) and cmax (=lane15 key).
__device__ __forceinline__ void warp_topk(const float4& me, int q, int lane,
                                          const int* saddr, int T,
                                          unsigned long long& lkey,
                                          unsigned long long& cmax) {
    unsigned long long mykey = ~0ULL;
    if (lane < T) mykey = cand_key(me, q, g_binpts[saddr[lane]]);
#pragma unroll
    for (int k = 2; k <= 32; k <<= 1) {
#pragma unroll
        for (int jj = k >> 1; jj > 0; jj >>= 1) {
            unsigned long long other = shflx64(mykey, jj);
            bool tmin = (((lane & jj) == 0) == ((lane & k) == 0));
            mykey = tmin ? min(mykey, other) : max(mykey, other);
        }
    }
    lkey = mykey;
    cmax = __shfl_sync(FULLM, lkey, 15);

    const int R = (T + 31) >> 5;
    for (int rb = 1; rb < R; rb += 4) {
        unsigned long long mk[4];
#pragma unroll
        for (int u = 0; u < 4; u++) {
            mk[u] = ~0ULL;
            int f = (rb + u) * 32 + lane;
            if (rb + u < R && f < T)
                mk[u] = cand_key(me, q, g_binpts[saddr[f]]);
        }
#pragma unroll
        for (int u = 0; u < 4; u++) {
            bool pend = (mk[u] < cmax);
            unsigned bal = __ballot_sync(FULLM, pend);
            while (bal) {
                int src = __ffs((int)bal) - 1;
                unsigned long long K = __shfl_sync(FULLM, mk[u], src);
                unsigned lt = __ballot_sync(FULLM, lkey < K) & 0xFFFFu;
                int pos = __popc(lt);
                unsigned long long up = __shfl_up_sync(FULLM, lkey, 1);
                lkey = (lane == pos) ? K : ((lane > pos) ? up : lkey);
                cmax = __shfl_sync(FULLM, lkey, 15);
                pend = pend && (lane != src) && (mk[u] < cmax);
                bal = __ballot_sync(FULLM, pend);
            }
        }
    }
}

// warp epilogue: write knn + distances, reduce minmax, atomics to target
__device__ __forceinline__ void warp_epilogue(const float4& me, int q, int lane,
                                              unsigned long long lkey,
                                              unsigned* mn_t, unsigned* mx_t) {
    unsigned lmn = 0x7F800000u, lmx = 0u;
    if (lane < 16) {
        int j = (int)(lkey & 0xFFFFFFFFULL);
        g_knn[q * KNN + lane] = j;
        float4 nb = g_pts[j];
        float dx = __fsub_rn(me.x, nb.x);
        float dy = __fsub_rn(me.y, nb.y);
        float d  = __fsqrt_rn(__fadd_rn(__fmul_rn(dx, dx),
                                        __fmul_rn(dy, dy)));
        g_d[q * KNN + lane] = d;
        unsigned b = __float_as_uint(d);
        lmn = b; lmx = b;
    }
    lmn = __reduce_min_sync(FULLM, lmn);
    lmx = __reduce_max_sync(FULLM, lmx);
    if (lane == 0) { atomicMin(mn_t, lmn); atomicMax(mx_t, lmx); }
}

// ---------------- K1: init + pack + bbox (block-reduced atomics) ------------
__global__ void prep_kernel(const float* __restrict__ c) {
    __shared__ unsigned red[4][8];
    int i = blockIdx.x * 256 + threadIdx.x;
    if (i < NCELL) g_bcnt[i] = 0;
    if (i == 0) { g_minmax[0] = 0x7F800000u; g_minmax[1] = 0u;
                  g_fbn = 0;
                  g_bbox[0] = 0xFFFFFFFFu; g_bbox[1] = 0u;
                  g_bbox[2] = 0xFFFFFFFFu; g_bbox[3] = 0u; }
    unsigned exn = 0xFFFFFFFFu, exx = 0u, eyn = 0xFFFFFFFFu, eyx = 0u;
    if (i < NN) {
        float x = c[2 * i], y = c[2 * i + 1];
        float sq = __fadd_rn(__fmul_rn(x, x), __fmul_rn(y, y));
        g_pts[i] = make_float4(x, y, sq, __int_as_float(i));
        unsigned ex = enc_ord(x), ey = enc_ord(y);
        exn = ex; exx = ex; eyn = ey; eyx = ey;
    }
    exn = __reduce_min_sync(FULLM, exn);
    exx = __reduce_max_sync(FULLM, exx);
    eyn = __reduce_min_sync(FULLM, eyn);
    eyx = __reduce_max_sync(FULLM, eyx);
    int w = threadIdx.x >> 5;
    if ((threadIdx.x & 31) == 0) {
        red[0][w] = exn; red[1][w] = exx; red[2][w] = eyn; red[3][w] = eyx;
    }
    __syncthreads();
    if (threadIdx.x < 4) {
        unsigned v = red[threadIdx.x][0];
        bool ismin = (threadIdx.x & 1) == 0;
#pragma unroll
        for (int k = 1; k < 8; k++)
            v = ismin ? min(v, red[threadIdx.x][k]) : max(v, red[threadIdx.x][k]);
        if (ismin) atomicMin(&g_bbox[threadIdx.x], v);
        else       atomicMax(&g_bbox[threadIdx.x], v);
    }
}

// ---------------- K2: bin fill (blocks < NBF) + x@W1 (rest) -----------------
#define NBF 63
__global__ void fill_mm1_kernel(const float* __restrict__ x,
                                const float* __restrict__ W1) {
    if (blockIdx.x < NBF) {
        int i = blockIdx.x * 256 + threadIdx.x;
        if (i >= NN) return;
        Grid g = load_grid();
        float4 p = g_pts[i];
        int cell = cell_y(g, p.y) * G + cell_x(g, p.x);
        int slot = atomicAdd(&g_bcnt[cell], 1);
        if (slot < CAP) g_binpts[cell * CAP + slot] = p;
        return;
    }
    __shared__ float sw[FIN * 64];
    int tid = threadIdx.x;
    for (int i = tid; i < FIN * 64; i += 256) sw[i] = W1[i];
    __syncthreads();
    int n = (blockIdx.x - NBF) * 4 + (tid >> 6);
    int f = tid & 63;
    const float* xr = x + n * FIN;
    float acc = 0.0f;
#pragma unroll
    for (int k = 0; k < FIN; k++) acc = fmaf(xr[k], sw[k * 64 + f], acc);
    g_bufA[n * 64 + f] = acc;
}

// ---------------- K3: warp-per-query exact KNN + edges ----------------------
// 5x5 window first; if certificate (2*smin)^2 fails, the SAME warp retries
// with the 9x9 window (certificate (4*smin)^2) while the rest of the launch
// keeps the chip busy — latency hidden, no idle-chip fallback kernel.
// Scalar ultimate guard (prob ~0) is deferred to a compacted-list kernel.
__global__ void __launch_bounds__(256, 5) knn_edge_kernel() {
    __shared__ int saddr[QPB][FSLOTCAP];
    __shared__ unsigned smn, smx;
    const int lane = threadIdx.x & 31;
    const int w = threadIdx.x >> 5;
    if (threadIdx.x == 0) { smn = 0x7F800000u; smx = 0u; }
    __syncthreads();

    const int q = blockIdx.x * QPB + w;
    const Grid g = load_grid();
    const float4 me = g_pts[q];
    const int cx = cell_x(g, me.x);
    const int cy = cell_y(g, me.y);

    // ---- 5x5 window scan ----
    int cnt = 0, cbase = 0;
    if (lane < 25) {
        int gx = cx + WDX[lane], gy = cy + WDY[lane];
        if (gx >= 0 && gx < G && gy >= 0 && gy < G) {
            int cid = gy * G + gx;
            cnt = min(g_bcnt[cid], CAP);
            cbase = cid * CAP;
        }
    }
    int pref = cnt;
#pragma unroll
    for (int off = 1; off < 32; off <<= 1) {
        int v = __shfl_up_sync(FULLM, pref, off);
        if (lane >= off) pref += v;
    }
    const int T = __shfl_sync(FULLM, pref, 24);
    bool retry9 = (T > FSLOTCAP);         // pathological; 9x9 path flags scalar

    unsigned long long lkey = ~0ULL, cmax = ~0ULL;
    if (!retry9) {
        int excl = pref - cnt;
        for (int k = 0; k < cnt; k++) saddr[w][excl + k] = cbase + k;
        __syncwarp();
        warp_topk(me, q, lane, saddr[w], T, lkey, cmax);
        // certificate: outside 5x5 window -> d2 >= (2*smin)^2
        float t16 = dec_ord((unsigned)(cmax >> 32));      // NaN if sentinel
        float bside = __fmul_rn(2.0f, g.smin);
        retry9 = !(t16 + 1e-4f < __fmul_rn(bside, bside)); // NaN -> retry
    }

    bool needscalar = false;
    if (retry9) {
        // ---- 9x9 window rebuild + retry (same warp, chip still busy) ----
        int total = 0;
        bool over = false;
#pragma unroll
        for (int ch = 0; ch < 3; ch++) {
            int idx = ch * 32 + lane;     // 0..95; valid < 81
            int c9 = 0, b9 = 0;
            if (idx < 81) {
                int gx = cx + (idx % 9) - 4, gy = cy + (idx / 9) - 4;
                if (gx >= 0 && gx < G && gy >= 0 && gy < G) {
                    int cid = gy * G + gx;
                    c9 = min(g_bcnt[cid], CAP);
                    b9 = cid * CAP;
                }
            }
            int p9 = c9;
#pragma unroll
            for (int off = 1; off < 32; off <<= 1) {
                int v = __shfl_up_sync(FULLM, p9, off);
                if (lane >= off) p9 += v;
            }
            int excl = total + p9 - c9;
            for (int k = 0; k < c9; k++) {
                if (excl + k < FSLOTCAP) saddr[w][excl + k] = b9 + k;
                else over = true;
            }
            total += __shfl_sync(FULLM, p9, 31);
        }
        over = __any_sync(FULLM, over) || (total > FSLOTCAP);
        __syncwarp();

        needscalar = over;
        if (!needscalar) {
            warp_topk(me, q, lane, saddr[w], total, lkey, cmax);
            // certificate: outside 9x9 window -> d2 >= (4*smin)^2
            float t16 = dec_ord((unsigned)(cmax >> 32));
            float bside = __fmul_rn(4.0f, g.smin);
            needscalar = !(t16 + 1e-4f < __fmul_rn(bside, bside));
        }
    }

    if (!needscalar) {
        warp_epilogue(me, q, lane, lkey, &smn, &smx);
    } else if (lane == 0) {
        int pos = atomicAdd(&g_fbn, 1);   // compacted scalar-guard list
        g_fbq[pos] = q;
    }
    __syncthreads();
    if (threadIdx.x == 0) {
        atomicMin(&g_minmax[0], smn);
        atomicMax(&g_minmax[1], smx);
    }
}

// ---------------- K4: scalar ultimate guard (expected empty) ----------------
__global__ void fallback_kernel() {
    int it = blockIdx.x * 256 + threadIdx.x;
    if (it >= g_fbn) return;
    const int q = g_fbq[it];
    const Grid g = load_grid();
    const float4 me = g_pts[q];
    const int cx = cell_x(g, me.x);
    const int cy = cell_y(g, me.y);

    unsigned long long keys[16];
#pragma unroll
    for (int t = 0; t < 16; t++) keys[t] = ~0ULL - (unsigned long long)t;
    unsigned long long cm = ~0ULL;
    for (int r = 0; r < G; r++) {
        if (r >= 2) {
            float b = (float)(r - 1) * g.smin;
            float thr = dec_ord((unsigned)(cm >> 32));
            if (b * b > thr + 1e-4f) break;
        }
        int y0 = cy - r, y1 = cy + r, x0 = cx - r, x1 = cx + r;
        for (int yy = max(y0, 0); yy <= min(y1, G - 1); yy++) {
            bool erow = (yy == y0) || (yy == y1);
            int xstep = (erow || r == 0) ? 1 : 2 * r;
            for (int xx = x0; xx <= x1; xx += xstep) {
                if (xx < 0 || xx >= G) continue;
                int cc = yy * G + xx;
                int c2 = min(g_bcnt[cc], CAP);
                const float4* bp = &g_binpts[cc * CAP];
                for (int p = 0; p < c2; p++) {
                    unsigned long long key = cand_key(me, q, bp[p]);
                    if (key < cm) {
                        unsigned long long nm = 0ULL;
#pragma unroll
                        for (int kk = 0; kk < 16; kk++) {
                            if (keys[kk] == cm) keys[kk] = key;
                            nm = max(nm, keys[kk]);
                        }
                        cm = nm;
                    }
                }
            }
        }
    }
#pragma unroll
    for (int i = 0; i < 15; i++)
#pragma unroll
        for (int t = 0; t < 15 - i; t++)
            if (keys[t] > keys[t + 1]) {
                unsigned long long tmp = keys[t];
                keys[t] = keys[t + 1];
                keys[t + 1] = tmp;
            }
    unsigned lmn = 0x7F800000u, lmx = 0u;
#pragma unroll
    for (int t = 0; t < 16; t++) {
        int j = (int)(keys[t] & 0xFFFFFFFFULL);
        g_knn[q * KNN + t] = j;
        float4 nb = g_pts[j];
        float dx = __fsub_rn(me.x, nb.x);
        float dy = __fsub_rn(me.y, nb.y);
        float d  = __fsqrt_rn(__fadd_rn(__fmul_rn(dx, dx),
                                        __fmul_rn(dy, dy)));
        g_d[q * KNN + t] = d;
        unsigned b = __float_as_uint(d);
        lmn = min(lmn, b);
        lmx = max(lmx, b);
    }
    atomicMin(&g_minmax[0], lmn);
    atomicMax(&g_minmax[1], lmx);
}

// ---------------- K5: edge weights + deg^{-1/2} (1 thread / edge) -----------
__global__ void deg_kernel() {
    int e = blockIdx.x * 256 + threadIdx.x;     // coalesced over edges
    float mx  = __uint_as_float(g_minmax[1]);
    float rng = __fsub_rn(mx, __uint_as_float(g_minmax[0]));
    float ew  = __fdiv_rn(__fsub_rn(mx, g_d[e]), rng);
    g_ew[e] = ew;
    float s = ew;
#pragma unroll
    for (int off = 8; off > 0; off >>= 1)
        s += __shfl_down_sync(FULLM, s, off, 16);
    if ((threadIdx.x & 15) == 0)
        g_dis[e >> 4] = rsqrtf(__fadd_rn(1.0f, s));   // +1 self-loop
}

// ---------------- K6: agg1 + relu + h1@W2 (16 nodes x 16 thr, float4) -------
#define ANP 16
__global__ void agg_mm2_kernel(const float* __restrict__ b1,
                               const float* __restrict__ W2) {
    __shared__ float4 sw4[HID * 16];      // W2 as [k][t] float4
    __shared__ float  sh1[ANP][HID];
    const int tid = threadIdx.x;          // 256
    const int r = tid >> 4, t = tid & 15;
    const float4* W24 = (const float4*)W2;
    for (int i = tid; i < HID * 16; i += 256) sw4[i] = W24[i];

    const int n = blockIdx.x * ANP + r;
    const float4* A4 = (const float4*)g_bufA;
    float disn = g_dis[n];
    float dd = __fmul_rn(disn, disn);
    float4 a = A4[n * 16 + t];
    float4 acc;
    acc.x = __fmul_rn(dd, a.x); acc.y = __fmul_rn(dd, a.y);
    acc.z = __fmul_rn(dd, a.z); acc.w = __fmul_rn(dd, a.w);
#pragma unroll
    for (int k = 0; k < KNN; k++) {
        int s = g_knn[n * KNN + k];
        float coef = __fmul_rn(__fmul_rn(g_dis[s], g_ew[n * KNN + k]), disn);
        float4 v = A4[s * 16 + t];
        acc.x = fmaf(coef, v.x, acc.x);
        acc.y = fmaf(coef, v.y, acc.y);
        acc.z = fmaf(coef, v.z, acc.z);
        acc.w = fmaf(coef, v.w, acc.w);
    }
    float4 bb = ((const float4*)b1)[t];
    sh1[r][4 * t + 0] = fmaxf(__fadd_rn(acc.x, bb.x), 0.0f);
    sh1[r][4 * t + 1] = fmaxf(__fadd_rn(acc.y, bb.y), 0.0f);
    sh1[r][4 * t + 2] = fmaxf(__fadd_rn(acc.z, bb.z), 0.0f);
    sh1[r][4 * t + 3] = fmaxf(__fadd_rn(acc.w, bb.w), 0.0f);
    __syncthreads();
    float4 acc2 = make_float4(0.0f, 0.0f, 0.0f, 0.0f);
#pragma unroll
    for (int k = 0; k < HID; k++) {
        float h = sh1[r][k];
        float4 wv = sw4[k * 16 + t];
        acc2.x = fmaf(h, wv.x, acc2.x);
        acc2.y = fmaf(h, wv.y, acc2.y);
        acc2.z = fmaf(h, wv.z, acc2.z);
        acc2.w = fmaf(h, wv.w, acc2.w);
    }
    ((float4*)g_bufB)[n * 16 + t] = acc2;
}

// ---------------- K7: agg2 + relu + FC head (16x16, shfl reduce) ------------
__global__ void final_kernel(const float* __restrict__ b2,
                             const float* __restrict__ wfc,
                             const float* __restrict__ bfc,
                             float* __restrict__ y) {
    const int tid = threadIdx.x;          // 256
    const int r = tid >> 4, t = tid & 15;
    const int n = blockIdx.x * ANP + r;
    const float4* B4 = (const float4*)g_bufB;
    float disn = g_dis[n];
    float dd = __fmul_rn(disn, disn);
    float4 a = B4[n * 16 + t];
    float4 acc;
    acc.x = __fmul_rn(dd, a.x); acc.y = __fmul_rn(dd, a.y);
    acc.z = __fmul_rn(dd, a.z); acc.w = __fmul_rn(dd, a.w);
#pragma unroll
    for (int k = 0; k < KNN; k++) {
        int s = g_knn[n * KNN + k];
        float coef = __fmul_rn(__fmul_rn(g_dis[s], g_ew[n * KNN + k]), disn);
        float4 v = B4[s * 16 + t];
        acc.x = fmaf(coef, v.x, acc.x);
        acc.y = fmaf(coef, v.y, acc.y);
        acc.z = fmaf(coef, v.z, acc.z);
        acc.w = fmaf(coef, v.w, acc.w);
    }
    float4 bb = ((const float4*)b2)[t];
    float4 wv = ((const float4*)wfc)[t];
    float p = 0.0f;
    p = fmaf(fmaxf(__fadd_rn(acc.x, bb.x), 0.0f), wv.x, p);
    p = fmaf(fmaxf(__fadd_rn(acc.y, bb.y), 0.0f), wv.y, p);
    p = fmaf(fmaxf(__fadd_rn(acc.z, bb.z), 0.0f), wv.z, p);
    p = fmaf(fmaxf(__fadd_rn(acc.w, bb.w), 0.0f), wv.w, p);
#pragma unroll
    for (int off = 8; off > 0; off >>= 1)
        p += __shfl_down_sync(FULLM, p, off, 16);
    if (t == 0) y[n] = p + bfc[0];
}

// ---------------- launch -----------------------------------------------------
extern "C" void kernel_launch(void* const* d_in, const int* in_sizes, int n_in,
                              void* d_out, int out_size) {
    const float* x   = (const float*)d_in[0];
    const float* c   = (const float*)d_in[1];
    const float* W1  = (const float*)d_in[2];
    const float* b1  = (const float*)d_in[3];
    const float* W2  = (const float*)d_in[4];
    const float* b2  = (const float*)d_in[5];
    const float* Wfc = (const float*)d_in[6];
    const float* bfc = (const float*)d_in[7];
    float* y = (float*)d_out;

    prep_kernel<<<63, 256>>>(c);                   // 0
    fill_mm1_kernel<<<NBF + NN / 4, 256>>>(x, W1); // 1
    knn_edge_kernel<<<NN / QPB, 256>>>();          // 2 (5x5 + inline 9x9)
    fallback_kernel<<<63, 256>>>();                // 3 (scalar guard; ~empty)
    deg_kernel<<<NN * KNN / 256, 256>>>();         // 4
    agg_mm2_kernel<<<NN / ANP, 256>>>(b1, W2);     // 5
    final_kernel<<<NN / ANP, 256>>>(b2, Wfc, bfc, y); // 6
}

// round 16
// speedup vs baseline: 1.0992x; 1.0358x over previous
#include <cuda_runtime.h>

#define NN 16000
#define KNN 16
#define FIN 32
#define HID 64
#define G 64
#define NCELL (G * G)
#define CAP 32            // max points per cell (lambda ~3.9)
#define QPB 8             // queries (=warps) per block
#define FSLOTCAP 768      // per-warp slot table (covers 5x5 and 9x9 windows)
#define FULLM 0xFFFFFFFFu

// ---------------- scratch (device globals; no allocation allowed) ----------
__device__ float4 g_pts[NN];              // {x, y, x^2+y^2, id-bits}
__device__ float4 g_binpts[NCELL * CAP];  // packed candidates per cell
__device__ int    g_bcnt[NCELL];          // per-cell fill counts
__device__ int    g_knn[NN * KNN];        // neighbor (src) indices (sorted)
__device__ float  g_d  [NN * KNN];        // edge distances
__device__ float  g_ew [NN * KNN];        // normalized inverted distances
__device__ float  g_dis[NN];              // deg^{-1/2}
__device__ unsigned g_minmax[2];          // [0]=min bits, [1]=max bits (d>=0)
__device__ unsigned g_bbox[4];            // ordered-uint minx,maxx,miny,maxy
__device__ float  g_bufA[NN * HID];       // x@W1
__device__ float  g_bufB[NN * HID];       // h1@W2

// 5x5 window offsets in center-out ring order (tightens cmax early)
__constant__ signed char WDX[25] = {0, -1,0,1,-1,1,-1,0,1,
                                    -2,-1,0,1,2, -2,2, -2,2, -2,2, -2,-1,0,1,2};
__constant__ signed char WDY[25] = {0, -1,-1,-1,0,0,1,1,1,
                                    -2,-2,-2,-2,-2, -1,-1, 0,0, 1,1, 2,2,2,2,2};

// ordered-uint map: monotone with float order (handles negatives)
__device__ __forceinline__ unsigned enc_ord(float f) {
    unsigned b = __float_as_uint(f);
    return (b & 0x80000000u) ? ~b : (b | 0x80000000u);
}
__device__ __forceinline__ float dec_ord(unsigned u) {
    return (u & 0x80000000u) ? __uint_as_float(u & 0x7FFFFFFFu)
                             : __uint_as_float(~u);
}

struct Grid { float minx, miny, invsx, invsy, smin; };
__device__ __forceinline__ Grid load_grid() {
    Grid g;
    g.minx = dec_ord(g_bbox[0]);
    float maxx = dec_ord(g_bbox[1]);
    g.miny = dec_ord(g_bbox[2]);
    float maxy = dec_ord(g_bbox[3]);
    float wx = fmaxf(maxx - g.minx, 1e-20f);
    float wy = fmaxf(maxy - g.miny, 1e-20f);
    g.invsx = (float)G / wx;
    g.invsy = (float)G / wy;
    g.smin  = fminf(wx, wy) / (float)G;
    return g;
}
__device__ __forceinline__ int cell_x(const Grid& g, float x) {
    int c = (int)((x - g.minx) * g.invsx);
    return min(max(c, 0), G - 1);
}
__device__ __forceinline__ int cell_y(const Grid& g, float y) {
    int c = (int)((y - g.miny) * g.invsy);
    return min(max(c, 0), G - 1);
}

// u64 shfl_xor helper
__device__ __forceinline__ unsigned long long shflx64(unsigned long long v,
                                                      int m) {
    unsigned lo = (unsigned)v, hi = (unsigned)(v >> 32);
    lo = __shfl_xor_sync(FULLM, lo, m);
    hi = __shfl_xor_sync(FULLM, hi, m);
    return ((unsigned long long)hi << 32) | lo;
}

// bit-exact d2 key vs query 'me'/'q' (shared by all paths)
__device__ __forceinline__ unsigned long long cand_key(const float4& me, int q,
                                                       const float4& pt) {
    int j = __float_as_int(pt.w);
    float dot = __fmaf_rn(me.y, pt.y, __fmul_rn(me.x, pt.x));
    float d2  = __fsub_rn(__fadd_rn(me.z, pt.z), __fmul_rn(2.0f, dot));
    unsigned long long key =
        ((unsigned long long)enc_ord(d2) << 32) | (unsigned)j;
    return (j == q) ? ~0ULL : key;
}

// warp bitonic round-0 + pipelined ballot-insert over slot table.
__device__ __forceinline__ void warp_topk(const float4& me, int q, int lane,
                                          const int* saddr, int T,
                                          unsigned long long& lkey,
                                          unsigned long long& cmax) {
    unsigned long long mykey = ~0ULL;
    if (lane < T) mykey = cand_key(me, q, g_binpts[saddr[lane]]);
#pragma unroll
    for (int k = 2; k <= 32; k <<= 1) {
#pragma unroll
        for (int jj = k >> 1; jj > 0; jj >>= 1) {
            unsigned long long other = shflx64(mykey, jj);
            bool tmin = (((lane & jj) == 0) == ((lane & k) == 0));
            mykey = tmin ? min(mykey, other) : max(mykey, other);
        }
    }
    lkey = mykey;
    cmax = __shfl_sync(FULLM, lkey, 15);

    const int R = (T + 31) >> 5;
    for (int rb = 1; rb < R; rb += 4) {
        unsigned long long mk[4];
#pragma unroll
        for (int u = 0; u < 4; u++) {
            mk[u] = ~0ULL;
            int f = (rb + u) * 32 + lane;
            if (rb + u < R && f < T)
                mk[u] = cand_key(me, q, g_binpts[saddr[f]]);
        }
#pragma unroll
        for (int u = 0; u < 4; u++) {
            bool pend = (mk[u] < cmax);
            unsigned bal = __ballot_sync(FULLM, pend);
            while (bal) {
                int src = __ffs((int)bal) - 1;
                unsigned long long K = __shfl_sync(FULLM, mk[u], src);
                unsigned lt = __ballot_sync(FULLM, lkey < K) & 0xFFFFu;
                int pos = __popc(lt);
                unsigned long long up = __shfl_up_sync(FULLM, lkey, 1);
                lkey = (lane == pos) ? K : ((lane > pos) ? up : lkey);
                cmax = __shfl_sync(FULLM, lkey, 15);
                pend = pend && (lane != src) && (mk[u] < cmax);
                bal = __ballot_sync(FULLM, pend);
            }
        }
    }
}

// warp epilogue: write knn + distances, reduce minmax, atomics to target
__device__ __forceinline__ void warp_epilogue(const float4& me, int q, int lane,
                                              unsigned long long lkey,
                                              unsigned* mn_t, unsigned* mx_t) {
    unsigned lmn = 0x7F800000u, lmx = 0u;
    if (lane < 16) {
        int j = (int)(lkey & 0xFFFFFFFFULL);
        g_knn[q * KNN + lane] = j;
        float4 nb = g_pts[j];
        float dx = __fsub_rn(me.x, nb.x);
        float dy = __fsub_rn(me.y, nb.y);
        float d  = __fsqrt_rn(__fadd_rn(__fmul_rn(dx, dx),
                                        __fmul_rn(dy, dy)));
        g_d[q * KNN + lane] = d;
        unsigned b = __float_as_uint(d);
        lmn = b; lmx = b;
    }
    lmn = __reduce_min_sync(FULLM, lmn);
    lmx = __reduce_max_sync(FULLM, lmx);
    if (lane == 0) { atomicMin(mn_t, lmn); atomicMax(mx_t, lmx); }
}

// ---------------- K1: init + pack + bbox (block-reduced atomics) ------------
__global__ void prep_kernel(const float* __restrict__ c) {
    __shared__ unsigned red[4][8];
    int i = blockIdx.x * 256 + threadIdx.x;
    if (i < NCELL) g_bcnt[i] = 0;
    if (i == 0) { g_minmax[0] = 0x7F800000u; g_minmax[1] = 0u;
                  g_bbox[0] = 0xFFFFFFFFu; g_bbox[1] = 0u;
                  g_bbox[2] = 0xFFFFFFFFu; g_bbox[3] = 0u; }
    unsigned exn = 0xFFFFFFFFu, exx = 0u, eyn = 0xFFFFFFFFu, eyx = 0u;
    if (i < NN) {
        float x = c[2 * i], y = c[2 * i + 1];
        float sq = __fadd_rn(__fmul_rn(x, x), __fmul_rn(y, y));
        g_pts[i] = make_float4(x, y, sq, __int_as_float(i));
        unsigned ex = enc_ord(x), ey = enc_ord(y);
        exn = ex; exx = ex; eyn = ey; eyx = ey;
    }
    exn = __reduce_min_sync(FULLM, exn);
    exx = __reduce_max_sync(FULLM, exx);
    eyn = __reduce_min_sync(FULLM, eyn);
    eyx = __reduce_max_sync(FULLM, eyx);
    int w = threadIdx.x >> 5;
    if ((threadIdx.x & 31) == 0) {
        red[0][w] = exn; red[1][w] = exx; red[2][w] = eyn; red[3][w] = eyx;
    }
    __syncthreads();
    if (threadIdx.x < 4) {
        unsigned v = red[threadIdx.x][0];
        bool ismin = (threadIdx.x & 1) == 0;
#pragma unroll
        for (int k = 1; k < 8; k++)
            v = ismin ? min(v, red[threadIdx.x][k]) : max(v, red[threadIdx.x][k]);
        if (ismin) atomicMin(&g_bbox[threadIdx.x], v);
        else       atomicMax(&g_bbox[threadIdx.x], v);
    }
}

// ---------------- K2: bin fill (blocks < NBF) + x@W1 (rest) -----------------
#define NBF 63
__global__ void fill_mm1_kernel(const float* __restrict__ x,
                                const float* __restrict__ W1) {
    if (blockIdx.x < NBF) {
        int i = blockIdx.x * 256 + threadIdx.x;
        if (i >= NN) return;
        Grid g = load_grid();
        float4 p = g_pts[i];
        int cell = cell_y(g, p.y) * G + cell_x(g, p.x);
        int slot = atomicAdd(&g_bcnt[cell], 1);
        if (slot < CAP) g_binpts[cell * CAP + slot] = p;
        return;
    }
    __shared__ float sw[FIN * 64];
    int tid = threadIdx.x;
    for (int i = tid; i < FIN * 64; i += 256) sw[i] = W1[i];
    __syncthreads();
    int n = (blockIdx.x - NBF) * 4 + (tid >> 6);
    int f = tid & 63;
    const float* xr = x + n * FIN;
    float acc = 0.0f;
#pragma unroll
    for (int k = 0; k < FIN; k++) acc = fmaf(xr[k], sw[k * 64 + f], acc);
    g_bufA[n * 64 + f] = acc;
}

// ---------------- K3: warp-per-query exact KNN + edges ----------------------
// 5x5 window; certificate fail -> same-warp 9x9 retry; fail again (prob ~0)
// -> lane-0 scalar full ring walk inline (chip still busy with other warps).
__global__ void __launch_bounds__(256, 5) knn_edge_kernel() {
    __shared__ int saddr[QPB][FSLOTCAP];
    __shared__ unsigned smn, smx;
    const int lane = threadIdx.x & 31;
    const int w = threadIdx.x >> 5;
    if (threadIdx.x == 0) { smn = 0x7F800000u; smx = 0u; }
    __syncthreads();

    const int q = blockIdx.x * QPB + w;
    const Grid g = load_grid();
    const float4 me = g_pts[q];
    const int cx = cell_x(g, me.x);
    const int cy = cell_y(g, me.y);

    // ---- 5x5 window scan ----
    int cnt = 0, cbase = 0;
    if (lane < 25) {
        int gx = cx + WDX[lane], gy = cy + WDY[lane];
        if (gx >= 0 && gx < G && gy >= 0 && gy < G) {
            int cid = gy * G + gx;
            cnt = min(g_bcnt[cid], CAP);
            cbase = cid * CAP;
        }
    }
    int pref = cnt;
#pragma unroll
    for (int off = 1; off < 32; off <<= 1) {
        int v = __shfl_up_sync(FULLM, pref, off);
        if (lane >= off) pref += v;
    }
    const int T = __shfl_sync(FULLM, pref, 24);
    bool retry9 = (T > FSLOTCAP);

    unsigned long long lkey = ~0ULL, cmax = ~0ULL;
    if (!retry9) {
        int excl = pref - cnt;
        for (int k = 0; k < cnt; k++) saddr[w][excl + k] = cbase + k;
        __syncwarp();
        warp_topk(me, q, lane, saddr[w], T, lkey, cmax);
        float t16 = dec_ord((unsigned)(cmax >> 32));      // NaN if sentinel
        float bside = __fmul_rn(2.0f, g.smin);
        retry9 = !(t16 + 1e-4f < __fmul_rn(bside, bside)); // NaN -> retry
    }

    bool needscalar = false;
    if (retry9) {
        // ---- 9x9 window rebuild + retry ----
        int total = 0;
        bool over = false;
#pragma unroll
        for (int ch = 0; ch < 3; ch++) {
            int idx = ch * 32 + lane;     // 0..95; valid < 81
            int c9 = 0, b9 = 0;
            if (idx < 81) {
                int gx = cx + (idx % 9) - 4, gy = cy + (idx / 9) - 4;
                if (gx >= 0 && gx < G && gy >= 0 && gy < G) {
                    int cid = gy * G + gx;
                    c9 = min(g_bcnt[cid], CAP);
                    b9 = cid * CAP;
                }
            }
            int p9 = c9;
#pragma unroll
            for (int off = 1; off < 32; off <<= 1) {
                int v = __shfl_up_sync(FULLM, p9, off);
                if (lane >= off) p9 += v;
            }
            int excl = total + p9 - c9;
            for (int k = 0; k < c9; k++) {
                if (excl + k < FSLOTCAP) saddr[w][excl + k] = b9 + k;
                else over = true;
            }
            total += __shfl_sync(FULLM, p9, 31);
        }
        over = __any_sync(FULLM, over) || (total > FSLOTCAP);
        __syncwarp();

        needscalar = over;
        if (!needscalar) {
            warp_topk(me, q, lane, saddr[w], total, lkey, cmax);
            float t16 = dec_ord((unsigned)(cmax >> 32));
            float bside = __fmul_rn(4.0f, g.smin);
            needscalar = !(t16 + 1e-4f < __fmul_rn(bside, bside));
        }
    }

    if (!needscalar) {
        warp_epilogue(me, q, lane, lkey, &smn, &smx);
    } else if (lane == 0) {
        // ultimate guard: exact scalar expanding ring walk (prob ~0)
        unsigned long long keys[16];
#pragma unroll
        for (int t = 0; t < 16; t++) keys[t] = ~0ULL - (unsigned long long)t;
        unsigned long long cm = ~0ULL;
        for (int r = 0; r < G; r++) {
            if (r >= 2) {
                float b = (float)(r - 1) * g.smin;
                float thr = dec_ord((unsigned)(cm >> 32));
                if (b * b > thr + 1e-4f) break;
            }
            int y0 = cy - r, y1 = cy + r, x0 = cx - r, x1 = cx + r;
            for (int yy = max(y0, 0); yy <= min(y1, G - 1); yy++) {
                bool erow = (yy == y0) || (yy == y1);
                int xstep = (erow || r == 0) ? 1 : 2 * r;
                for (int xx = x0; xx <= x1; xx += xstep) {
                    if (xx < 0 || xx >= G) continue;
                    int cc = yy * G + xx;
                    int c2 = min(g_bcnt[cc], CAP);
                    const float4* bp = &g_binpts[cc * CAP];
                    for (int p = 0; p < c2; p++) {
                        unsigned long long key = cand_key(me, q, bp[p]);
                        if (key < cm) {
                            unsigned long long nm = 0ULL;
#pragma unroll
                            for (int kk = 0; kk < 16; kk++) {
                                if (keys[kk] == cm) keys[kk] = key;
                                nm = max(nm, keys[kk]);
                            }
                            cm = nm;
                        }
                    }
                }
            }
        }
#pragma unroll
        for (int i = 0; i < 15; i++)
#pragma unroll
            for (int t = 0; t < 15 - i; t++)
                if (keys[t] > keys[t + 1]) {
                    unsigned long long tmp = keys[t];
                    keys[t] = keys[t + 1];
                    keys[t + 1] = tmp;
                }
        unsigned lmn = 0x7F800000u, lmx = 0u;
#pragma unroll
        for (int t = 0; t < 16; t++) {
            int j = (int)(keys[t] & 0xFFFFFFFFULL);
            g_knn[q * KNN + t] = j;
            float4 nb = g_pts[j];
            float dx = __fsub_rn(me.x, nb.x);
            float dy = __fsub_rn(me.y, nb.y);
            float d  = __fsqrt_rn(__fadd_rn(__fmul_rn(dx, dx),
                                            __fmul_rn(dy, dy)));
            g_d[q * KNN + t] = d;
            unsigned b = __float_as_uint(d);
            lmn = min(lmn, b);
            lmx = max(lmx, b);
        }
        atomicMin(&smn, lmn);
        atomicMax(&smx, lmx);
    }
    __syncthreads();
    if (threadIdx.x == 0) {
        atomicMin(&g_minmax[0], smn);
        atomicMax(&g_minmax[1], smx);
    }
}

// ---------------- K4: edge weights + deg^{-1/2} (1 thread / edge) -----------
__global__ void deg_kernel() {
    int e = blockIdx.x * 256 + threadIdx.x;     // coalesced over edges
    float mx  = __uint_as_float(g_minmax[1]);
    float rng = __fsub_rn(mx, __uint_as_float(g_minmax[0]));
    float ew  = __fdiv_rn(__fsub_rn(mx, g_d[e]), rng);
    g_ew[e] = ew;
    float s = ew;
#pragma unroll
    for (int off = 8; off > 0; off >>= 1)
        s += __shfl_down_sync(FULLM, s, off, 16);
    if ((threadIdx.x & 15) == 0)
        g_dis[e >> 4] = rsqrtf(__fadd_rn(1.0f, s));   // +1 self-loop
}

// ---------------- K5: agg1 + relu + h1@W2 (16 nodes x 16 thr, float4) -------
// Coefs de-duplicated: lane t computes coef_t once; k-loop broadcasts
// (coef, s) via width-16 shfl. FMA k-order unchanged -> bit-identical.
#define ANP 16
__global__ void agg_mm2_kernel(const float* __restrict__ b1,
                               const float* __restrict__ W2) {
    __shared__ float4 sw4[HID * 16];      // W2 as [k][t] float4
    __shared__ float  sh1[ANP][HID];
    const int tid = threadIdx.x;          // 256
    const int r = tid >> 4, t = tid & 15;
    const float4* W24 = (const float4*)W2;
    for (int i = tid; i < HID * 16; i += 256) sw4[i] = W24[i];

    const int n = blockIdx.x * ANP + r;
    const float4* A4 = (const float4*)g_bufA;
    float disn = g_dis[n];
    float dd = __fmul_rn(disn, disn);

    // lane t owns neighbor t
    int   s_t  = g_knn[n * KNN + t];
    float cf_t = __fmul_rn(__fmul_rn(g_dis[s_t], g_ew[n * KNN + t]), disn);

    float4 a = A4[n * 16 + t];
    float4 acc;
    acc.x = __fmul_rn(dd, a.x); acc.y = __fmul_rn(dd, a.y);
    acc.z = __fmul_rn(dd, a.z); acc.w = __fmul_rn(dd, a.w);
#pragma unroll
    for (int k = 0; k < KNN; k++) {
        float coef = __shfl_sync(FULLM, cf_t, k, 16);
        int   s    = __shfl_sync(FULLM, s_t,  k, 16);
        float4 v = A4[s * 16 + t];
        acc.x = fmaf(coef, v.x, acc.x);
        acc.y = fmaf(coef, v.y, acc.y);
        acc.z = fmaf(coef, v.z, acc.z);
        acc.w = fmaf(coef, v.w, acc.w);
    }
    float4 bb = ((const float4*)b1)[t];
    sh1[r][4 * t + 0] = fmaxf(__fadd_rn(acc.x, bb.x), 0.0f);
    sh1[r][4 * t + 1] = fmaxf(__fadd_rn(acc.y, bb.y), 0.0f);
    sh1[r][4 * t + 2] = fmaxf(__fadd_rn(acc.z, bb.z), 0.0f);
    sh1[r][4 * t + 3] = fmaxf(__fadd_rn(acc.w, bb.w), 0.0f);
    __syncthreads();
    float4 acc2 = make_float4(0.0f, 0.0f, 0.0f, 0.0f);
#pragma unroll
    for (int k = 0; k < HID; k++) {
        float h = sh1[r][k];
        float4 wv = sw4[k * 16 + t];
        acc2.x = fmaf(h, wv.x, acc2.x);
        acc2.y = fmaf(h, wv.y, acc2.y);
        acc2.z = fmaf(h, wv.z, acc2.z);
        acc2.w = fmaf(h, wv.w, acc2.w);
    }
    ((float4*)g_bufB)[n * 16 + t] = acc2;
}

// ---------------- K6: agg2 + relu + FC head (16x16, shfl reduce) ------------
__global__ void final_kernel(const float* __restrict__ b2,
                             const float* __restrict__ wfc,
                             const float* __restrict__ bfc,
                             float* __restrict__ y) {
    const int tid = threadIdx.x;          // 256
    const int r = tid >> 4, t = tid & 15;
    const int n = blockIdx.x * ANP + r;
    const float4* B4 = (const float4*)g_bufB;
    float disn = g_dis[n];
    float dd = __fmul_rn(disn, disn);

    int   s_t  = g_knn[n * KNN + t];
    float cf_t = __fmul_rn(__fmul_rn(g_dis[s_t], g_ew[n * KNN + t]), disn);

    float4 a = B4[n * 16 + t];
    float4 acc;
    acc.x = __fmul_rn(dd, a.x); acc.y = __fmul_rn(dd, a.y);
    acc.z = __fmul_rn(dd, a.z); acc.w = __fmul_rn(dd, a.w);
#pragma unroll
    for (int k = 0; k < KNN; k++) {
        float coef = __shfl_sync(FULLM, cf_t, k, 16);
        int   s    = __shfl_sync(FULLM, s_t,  k, 16);
        float4 v = B4[s * 16 + t];
        acc.x = fmaf(coef, v.x, acc.x);
        acc.y = fmaf(coef, v.y, acc.y);
        acc.z = fmaf(coef, v.z, acc.z);
        acc.w = fmaf(coef, v.w, acc.w);
    }
    float4 bb = ((const float4*)b2)[t];
    float4 wv = ((const float4*)wfc)[t];
    float p = 0.0f;
    p = fmaf(fmaxf(__fadd_rn(acc.x, bb.x), 0.0f), wv.x, p);
    p = fmaf(fmaxf(__fadd_rn(acc.y, bb.y), 0.0f), wv.y, p);
    p = fmaf(fmaxf(__fadd_rn(acc.z, bb.z), 0.0f), wv.z, p);
    p = fmaf(fmaxf(__fadd_rn(acc.w, bb.w), 0.0f), wv.w, p);
#pragma unroll
    for (int off = 8; off > 0; off >>= 1)
        p += __shfl_down_sync(FULLM, p, off, 16);
    if (t == 0) y[n] = p + bfc[0];
}

// ---------------- launch -----------------------------------------------------
extern "C" void kernel_launch(void* const* d_in, const int* in_sizes, int n_in,
                              void* d_out, int out_size) {
    const float* x   = (const float*)d_in[0];
    const float* c   = (const float*)d_in[1];
    const float* W1  = (const float*)d_in[2];
    const float* b1  = (const float*)d_in[3];
    const float* W2  = (const float*)d_in[4];
    const float* b2  = (const float*)d_in[5];
    const float* Wfc = (const float*)d_in[6];
    const float* bfc = (const float*)d_in[7];
    float* y = (float*)d_out;

    prep_kernel<<<63, 256>>>(c);                   // 0
    fill_mm1_kernel<<<NBF + NN / 4, 256>>>(x, W1); // 1
    knn_edge_kernel<<<NN / QPB, 256>>>();          // 2 (5x5 + 9x9 + guard)
    deg_kernel<<<NN * KNN / 256, 256>>>();         // 3 (profiled)
    agg_mm2_kernel<<<NN / ANP, 256>>>(b1, W2);     // 4
    final_kernel<<<NN / ANP, 256>>>(b2, Wfc, bfc, y); // 5
}

// round 17
// speedup vs baseline: 1.1245x; 1.0230x over previous
#include <cuda_runtime.h>

#define NN 16000
#define KNN 16
#define FIN 32
#define HID 64
#define G 64
#define NCELL (G * G)
#define CAP 32            // max points per cell (lambda ~3.9)
#define QPB 8             // queries (=warps) per block
#define FSLOTCAP 768      // per-warp slot table (covers 5x5 and 9x9 windows)
#define FULLM 0xFFFFFFFFu

// ---------------- scratch (device globals; no allocation allowed) ----------
__device__ float4 g_pts[NN];              // {x, y, x^2+y^2, id-bits}
__device__ float4 g_binpts[NCELL * CAP];  // packed candidates per cell
__device__ int    g_bcnt[NCELL];          // per-cell fill counts
__device__ int    g_knn[NN * KNN];        // neighbor (src) indices (sorted)
__device__ float  g_d  [NN * KNN];        // edge distances
__device__ float  g_dis[NN];              // deg^{-1/2}
__device__ unsigned g_minmax[2];          // [0]=min bits, [1]=max bits (d>=0)
__device__ unsigned g_bbox[4];            // ordered-uint minx,maxx,miny,maxy
__device__ float  g_bufA[NN * HID];       // x@W1
__device__ float  g_bufB[NN * HID];       // h1@W2

// 5x5 window offsets in center-out ring order (tightens cmax early)
__constant__ signed char WDX[25] = {0, -1,0,1,-1,1,-1,0,1,
                                    -2,-1,0,1,2, -2,2, -2,2, -2,2, -2,-1,0,1,2};
__constant__ signed char WDY[25] = {0, -1,-1,-1,0,0,1,1,1,
                                    -2,-2,-2,-2,-2, -1,-1, 0,0, 1,1, 2,2,2,2,2};

// ordered-uint map: monotone with float order (handles negatives)
__device__ __forceinline__ unsigned enc_ord(float f) {
    unsigned b = __float_as_uint(f);
    return (b & 0x80000000u) ? ~b : (b | 0x80000000u);
}
__device__ __forceinline__ float dec_ord(unsigned u) {
    return (u & 0x80000000u) ? __uint_as_float(u & 0x7FFFFFFFu)
                             : __uint_as_float(~u);
}

struct Grid { float minx, miny, invsx, invsy, smin; };
__device__ __forceinline__ Grid load_grid() {
    Grid g;
    g.minx = dec_ord(g_bbox[0]);
    float maxx = dec_ord(g_bbox[1]);
    g.miny = dec_ord(g_bbox[2]);
    float maxy = dec_ord(g_bbox[3]);
    float wx = fmaxf(maxx - g.minx, 1e-20f);
    float wy = fmaxf(maxy - g.miny, 1e-20f);
    g.invsx = (float)G / wx;
    g.invsy = (float)G / wy;
    g.smin  = fminf(wx, wy) / (float)G;
    return g;
}
__device__ __forceinline__ int cell_x(const Grid& g, float x) {
    int c = (int)((x - g.minx) * g.invsx);
    return min(max(c, 0), G - 1);
}
__device__ __forceinline__ int cell_y(const Grid& g, float y) {
    int c = (int)((y - g.miny) * g.invsy);
    return min(max(c, 0), G - 1);
}

// u64 shfl helpers
__device__ __forceinline__ unsigned long long shflx64(unsigned long long v,
                                                      int m) {
    unsigned lo = (unsigned)v, hi = (unsigned)(v >> 32);
    lo = __shfl_xor_sync(FULLM, lo, m);
    hi = __shfl_xor_sync(FULLM, hi, m);
    return ((unsigned long long)hi << 32) | lo;
}
__device__ __forceinline__ unsigned long long shfli64(unsigned long long v,
                                                      int src) {
    unsigned lo = (unsigned)v, hi = (unsigned)(v >> 32);
    lo = __shfl_sync(FULLM, lo, src);
    hi = __shfl_sync(FULLM, hi, src);
    return ((unsigned long long)hi << 32) | lo;
}

// bit-exact d2 key vs query 'me'/'q' (shared by all paths)
__device__ __forceinline__ unsigned long long cand_key(const float4& me, int q,
                                                       const float4& pt) {
    int j = __float_as_int(pt.w);
    float dot = __fmaf_rn(me.y, pt.y, __fmul_rn(me.x, pt.x));
    float d2  = __fsub_rn(__fadd_rn(me.z, pt.z), __fmul_rn(2.0f, dot));
    unsigned long long key =
        ((unsigned long long)enc_ord(d2) << 32) | (unsigned)j;
    return (j == q) ? ~0ULL : key;
}

// full 32-lane ascending bitonic sort of one key per lane
__device__ __forceinline__ unsigned long long bitonic32(unsigned long long v,
                                                        int lane) {
#pragma unroll
    for (int k = 2; k <= 32; k <<= 1)
#pragma unroll
        for (int jj = k >> 1; jj > 0; jj >>= 1) {
            unsigned long long other = shflx64(v, jj);
            bool tmin = (((lane & jj) == 0) == ((lane & k) == 0));
            v = tmin ? min(v, other) : max(v, other);
        }
    return v;
}

// warp top-16: bitonic round-0, then per-round sort32 + bitonic merge-16.
// lkey (lanes 0..15) = sorted min-16 ascending; cmax = lane-15 key.
__device__ __forceinline__ void warp_topk(const float4& me, int q, int lane,
                                          const int* saddr, int T,
                                          unsigned long long& lkey,
                                          unsigned long long& cmax) {
    unsigned long long mykey = ~0ULL;
    if (lane < T) mykey = cand_key(me, q, g_binpts[saddr[lane]]);
    lkey = bitonic32(mykey, lane);
    cmax = shfli64(lkey, 15);

    const int R = (T + 31) >> 5;
    for (int rb = 1; rb < R; rb += 4) {
        unsigned long long mk[4];
#pragma unroll
        for (int u = 0; u < 4; u++) {
            mk[u] = ~0ULL;
            int f = (rb + u) * 32 + lane;
            if (rb + u < R && f < T)
                mk[u] = cand_key(me, q, g_binpts[saddr[f]]);
        }
#pragma unroll
        for (int u = 0; u < 4; u++) {
            if (!__any_sync(FULLM, mk[u] < cmax)) continue;
            // sort the 32 new keys; B[0..15] = their 16 smallest (ascending)
            unsigned long long b = bitonic32(mk[u], lane);
            // L[i] = min(A[i], B[15-i]) = 16 smallest of union (bitonic)
            unsigned long long brev = shfli64(b, (15 - lane) & 31);
            unsigned long long L = min(lkey, brev);
#pragma unroll
            for (int jj = 8; jj > 0; jj >>= 1) {
                unsigned long long other = shflx64(L, jj);
                L = ((lane & jj) == 0) ? min(L, other) : max(L, other);
            }
            lkey = L;                     // lanes 0..15 valid
            cmax = shfli64(lkey, 15);
        }
    }
}

// warp epilogue: write knn + distances, reduce minmax, atomics to target
__device__ __forceinline__ void warp_epilogue(const float4& me, int q, int lane,
                                              unsigned long long lkey,
                                              unsigned* mn_t, unsigned* mx_t) {
    unsigned lmn = 0x7F800000u, lmx = 0u;
    if (lane < 16) {
        int j = (int)(lkey & 0xFFFFFFFFULL);
        g_knn[q * KNN + lane] = j;
        float4 nb = g_pts[j];
        float dx = __fsub_rn(me.x, nb.x);
        float dy = __fsub_rn(me.y, nb.y);
        float d  = __fsqrt_rn(__fadd_rn(__fmul_rn(dx, dx),
                                        __fmul_rn(dy, dy)));
        g_d[q * KNN + lane] = d;
        unsigned b = __float_as_uint(d);
        lmn = b; lmx = b;
    }
    lmn = __reduce_min_sync(FULLM, lmn);
    lmx = __reduce_max_sync(FULLM, lmx);
    if (lane == 0) { atomicMin(mn_t, lmn); atomicMax(mx_t, lmx); }
}

// ---------------- K1: init + pack + bbox (block-reduced atomics) ------------
__global__ void prep_kernel(const float* __restrict__ c) {
    __shared__ unsigned red[4][8];
    int i = blockIdx.x * 256 + threadIdx.x;
    if (i < NCELL) g_bcnt[i] = 0;
    if (i == 0) { g_minmax[0] = 0x7F800000u; g_minmax[1] = 0u;
                  g_bbox[0] = 0xFFFFFFFFu; g_bbox[1] = 0u;
                  g_bbox[2] = 0xFFFFFFFFu; g_bbox[3] = 0u; }
    unsigned exn = 0xFFFFFFFFu, exx = 0u, eyn = 0xFFFFFFFFu, eyx = 0u;
    if (i < NN) {
        float x = c[2 * i], y = c[2 * i + 1];
        float sq = __fadd_rn(__fmul_rn(x, x), __fmul_rn(y, y));
        g_pts[i] = make_float4(x, y, sq, __int_as_float(i));
        unsigned ex = enc_ord(x), ey = enc_ord(y);
        exn = ex; exx = ex; eyn = ey; eyx = ey;
    }
    exn = __reduce_min_sync(FULLM, exn);
    exx = __reduce_max_sync(FULLM, exx);
    eyn = __reduce_min_sync(FULLM, eyn);
    eyx = __reduce_max_sync(FULLM, eyx);
    int w = threadIdx.x >> 5;
    if ((threadIdx.x & 31) == 0) {
        red[0][w] = exn; red[1][w] = exx; red[2][w] = eyn; red[3][w] = eyx;
    }
    __syncthreads();
    if (threadIdx.x < 4) {
        unsigned v = red[threadIdx.x][0];
        bool ismin = (threadIdx.x & 1) == 0;
#pragma unroll
        for (int k = 1; k < 8; k++)
            v = ismin ? min(v, red[threadIdx.x][k]) : max(v, red[threadIdx.x][k]);
        if (ismin) atomicMin(&g_bbox[threadIdx.x], v);
        else       atomicMax(&g_bbox[threadIdx.x], v);
    }
}

// ---------------- K2: bin fill (blocks < NBF) + x@W1 (rest) -----------------
#define NBF 63
__global__ void fill_mm1_kernel(const float* __restrict__ x,
                                const float* __restrict__ W1) {
    if (blockIdx.x < NBF) {
        int i = blockIdx.x * 256 + threadIdx.x;
        if (i >= NN) return;
        Grid g = load_grid();
        float4 p = g_pts[i];
        int cell = cell_y(g, p.y) * G + cell_x(g, p.x);
        int slot = atomicAdd(&g_bcnt[cell], 1);
        if (slot < CAP) g_binpts[cell * CAP + slot] = p;
        return;
    }
    __shared__ float sw[FIN * 64];
    int tid = threadIdx.x;
    for (int i = tid; i < FIN * 64; i += 256) sw[i] = W1[i];
    __syncthreads();
    int n = (blockIdx.x - NBF) * 4 + (tid >> 6);
    int f = tid & 63;
    const float* xr = x + n * FIN;
    float acc = 0.0f;
#pragma unroll
    for (int k = 0; k < FIN; k++) acc = fmaf(xr[k], sw[k * 64 + f], acc);
    g_bufA[n * 64 + f] = acc;
}

// ---------------- K3: warp-per-query exact KNN + edges ----------------------
// 5x5 window; certificate fail -> same-warp 9x9 retry; fail again (prob ~0)
// -> lane-0 scalar full ring walk inline (chip still busy with other warps).
__global__ void __launch_bounds__(256, 5) knn_edge_kernel() {
    __shared__ int saddr[QPB][FSLOTCAP];
    __shared__ unsigned smn, smx;
    const int lane = threadIdx.x & 31;
    const int w = threadIdx.x >> 5;
    if (threadIdx.x == 0) { smn = 0x7F800000u; smx = 0u; }
    __syncthreads();

    const int q = blockIdx.x * QPB + w;
    const Grid g = load_grid();
    const float4 me = g_pts[q];
    const int cx = cell_x(g, me.x);
    const int cy = cell_y(g, me.y);

    // ---- 5x5 window scan ----
    int cnt = 0, cbase = 0;
    if (lane < 25) {
        int gx = cx + WDX[lane], gy = cy + WDY[lane];
        if (gx >= 0 && gx < G && gy >= 0 && gy < G) {
            int cid = gy * G + gx;
            cnt = min(g_bcnt[cid], CAP);
            cbase = cid * CAP;
        }
    }
    int pref = cnt;
#pragma unroll
    for (int off = 1; off < 32; off <<= 1) {
        int v = __shfl_up_sync(FULLM, pref, off);
        if (lane >= off) pref += v;
    }
    const int T = __shfl_sync(FULLM, pref, 24);
    bool retry9 = (T > FSLOTCAP);

    unsigned long long lkey = ~0ULL, cmax = ~0ULL;
    if (!retry9) {
        int excl = pref - cnt;
        for (int k = 0; k < cnt; k++) saddr[w][excl + k] = cbase + k;
        __syncwarp();
        warp_topk(me, q, lane, saddr[w], T, lkey, cmax);
        float t16 = dec_ord((unsigned)(cmax >> 32));      // NaN if sentinel
        float bside = __fmul_rn(2.0f, g.smin);
        retry9 = !(t16 + 1e-4f < __fmul_rn(bside, bside)); // NaN -> retry
    }

    bool needscalar = false;
    if (retry9) {
        // ---- 9x9 window rebuild + retry ----
        int total = 0;
        bool over = false;
#pragma unroll
        for (int ch = 0; ch < 3; ch++) {
            int idx = ch * 32 + lane;     // 0..95; valid < 81
            int c9 = 0, b9 = 0;
            if (idx < 81) {
                int gx = cx + (idx % 9) - 4, gy = cy + (idx / 9) - 4;
                if (gx >= 0 && gx < G && gy >= 0 && gy < G) {
                    int cid = gy * G + gx;
                    c9 = min(g_bcnt[cid], CAP);
                    b9 = cid * CAP;
                }
            }
            int p9 = c9;
#pragma unroll
            for (int off = 1; off < 32; off <<= 1) {
                int v = __shfl_up_sync(FULLM, p9, off);
                if (lane >= off) p9 += v;
            }
            int excl = total + p9 - c9;
            for (int k = 0; k < c9; k++) {
                if (excl + k < FSLOTCAP) saddr[w][excl + k] = b9 + k;
                else over = true;
            }
            total += __shfl_sync(FULLM, p9, 31);
        }
        over = __any_sync(FULLM, over) || (total > FSLOTCAP);
        __syncwarp();

        needscalar = over;
        if (!needscalar) {
            warp_topk(me, q, lane, saddr[w], total, lkey, cmax);
            float t16 = dec_ord((unsigned)(cmax >> 32));
            float bside = __fmul_rn(4.0f, g.smin);
            needscalar = !(t16 + 1e-4f < __fmul_rn(bside, bside));
        }
    }

    if (!needscalar) {
        warp_epilogue(me, q, lane, lkey, &smn, &smx);
    } else if (lane == 0) {
        // ultimate guard: exact scalar expanding ring walk (prob ~0)
        unsigned long long keys[16];
#pragma unroll
        for (int t = 0; t < 16; t++) keys[t] = ~0ULL - (unsigned long long)t;
        unsigned long long cm = ~0ULL;
        for (int r = 0; r < G; r++) {
            if (r >= 2) {
                float b = (float)(r - 1) * g.smin;
                float thr = dec_ord((unsigned)(cm >> 32));
                if (b * b > thr + 1e-4f) break;
            }
            int y0 = cy - r, y1 = cy + r, x0 = cx - r, x1 = cx + r;
            for (int yy = max(y0, 0); yy <= min(y1, G - 1); yy++) {
                bool erow = (yy == y0) || (yy == y1);
                int xstep = (erow || r == 0) ? 1 : 2 * r;
                for (int xx = x0; xx <= x1; xx += xstep) {
                    if (xx < 0 || xx >= G) continue;
                    int cc = yy * G + xx;
                    int c2 = min(g_bcnt[cc], CAP);
                    const float4* bp = &g_binpts[cc * CAP];
                    for (int p = 0; p < c2; p++) {
                        unsigned long long key = cand_key(me, q, bp[p]);
                        if (key < cm) {
                            unsigned long long nm = 0ULL;
#pragma unroll
                            for (int kk = 0; kk < 16; kk++) {
                                if (keys[kk] == cm) keys[kk] = key;
                                nm = max(nm, keys[kk]);
                            }
                            cm = nm;
                        }
                    }
                }
            }
        }
#pragma unroll
        for (int i = 0; i < 15; i++)
#pragma unroll
            for (int t = 0; t < 15 - i; t++)
                if (keys[t] > keys[t + 1]) {
                    unsigned long long tmp = keys[t];
                    keys[t] = keys[t + 1];
                    keys[t + 1] = tmp;
                }
        unsigned lmn = 0x7F800000u, lmx = 0u;
#pragma unroll
        for (int t = 0; t < 16; t++) {
            int j = (int)(keys[t] & 0xFFFFFFFFULL);
            g_knn[q * KNN + t] = j;
            float4 nb = g_pts[j];
            float dx = __fsub_rn(me.x, nb.x);
            float dy = __fsub_rn(me.y, nb.y);
            float d  = __fsqrt_rn(__fadd_rn(__fmul_rn(dx, dx),
                                            __fmul_rn(dy, dy)));
            g_d[q * KNN + t] = d;
            unsigned b = __float_as_uint(d);
            lmn = min(lmn, b);
            lmx = max(lmx, b);
        }
        atomicMin(&smn, lmn);
        atomicMax(&smx, lmx);
    }
    __syncthreads();
    if (threadIdx.x == 0) {
        atomicMin(&g_minmax[0], smn);
        atomicMax(&g_minmax[1], smx);
    }
}

// ---------------- K4: deg^{-1/2} only (ew recomputed downstream) ------------
__global__ void deg_kernel() {
    int e = blockIdx.x * 256 + threadIdx.x;     // coalesced over edges
    float mx  = __uint_as_float(g_minmax[1]);
    float rng = __fsub_rn(mx, __uint_as_float(g_minmax[0]));
    float ew  = __fdiv_rn(__fsub_rn(mx, g_d[e]), rng);
    float s = ew;
#pragma unroll
    for (int off = 8; off > 0; off >>= 1)
        s += __shfl_down_sync(FULLM, s, off, 16);
    if ((threadIdx.x & 15) == 0)
        g_dis[e >> 4] = rsqrtf(__fadd_rn(1.0f, s));   // +1 self-loop
}

// ---------------- K5: agg1 + relu + h1@W2 (16 nodes x 16 thr, float4) -------
// Lane t owns neighbor t: recomputes ew_t from g_d (identical rounding),
// coef broadcast via width-16 shfl. FMA k-order unchanged -> bit-identical.
#define ANP 16
__global__ void agg_mm2_kernel(const float* __restrict__ b1,
                               const float* __restrict__ W2) {
    __shared__ float4 sw4[HID * 16];      // W2 as [k][t] float4
    __shared__ float  sh1[ANP][HID];
    const int tid = threadIdx.x;          // 256
    const int r = tid >> 4, t = tid & 15;
    const float4* W24 = (const float4*)W2;
    for (int i = tid; i < HID * 16; i += 256) sw4[i] = W24[i];

    const int n = blockIdx.x * ANP + r;
    const float4* A4 = (const float4*)g_bufA;
    float disn = g_dis[n];
    float dd = __fmul_rn(disn, disn);
    float mx  = __uint_as_float(g_minmax[1]);
    float rng = __fsub_rn(mx, __uint_as_float(g_minmax[0]));

    int   s_t  = g_knn[n * KNN + t];
    float ew_t = __fdiv_rn(__fsub_rn(mx, g_d[n * KNN + t]), rng);
    float cf_t = __fmul_rn(__fmul_rn(g_dis[s_t], ew_t), disn);

    float4 a = A4[n * 16 + t];
    float4 acc;
    acc.x = __fmul_rn(dd, a.x); acc.y = __fmul_rn(dd, a.y);
    acc.z = __fmul_rn(dd, a.z); acc.w = __fmul_rn(dd, a.w);
#pragma unroll
    for (int k = 0; k < KNN; k++) {
        float coef = __shfl_sync(FULLM, cf_t, k, 16);
        int   s    = __shfl_sync(FULLM, s_t,  k, 16);
        float4 v = A4[s * 16 + t];
        acc.x = fmaf(coef, v.x, acc.x);
        acc.y = fmaf(coef, v.y, acc.y);
        acc.z = fmaf(coef, v.z, acc.z);
        acc.w = fmaf(coef, v.w, acc.w);
    }
    float4 bb = ((const float4*)b1)[t];
    sh1[r][4 * t + 0] = fmaxf(__fadd_rn(acc.x, bb.x), 0.0f);
    sh1[r][4 * t + 1] = fmaxf(__fadd_rn(acc.y, bb.y), 0.0f);
    sh1[r][4 * t + 2] = fmaxf(__fadd_rn(acc.z, bb.z), 0.0f);
    sh1[r][4 * t + 3] = fmaxf(__fadd_rn(acc.w, bb.w), 0.0f);
    __syncthreads();
    float4 acc2 = make_float4(0.0f, 0.0f, 0.0f, 0.0f);
#pragma unroll
    for (int k = 0; k < HID; k++) {
        float h = sh1[r][k];
        float4 wv = sw4[k * 16 + t];
        acc2.x = fmaf(h, wv.x, acc2.x);
        acc2.y = fmaf(h, wv.y, acc2.y);
        acc2.z = fmaf(h, wv.z, acc2.z);
        acc2.w = fmaf(h, wv.w, acc2.w);
    }
    ((float4*)g_bufB)[n * 16 + t] = acc2;
}

// ---------------- K6: agg2 + relu + FC head (16x16, shfl reduce) ------------
__global__ void final_kernel(const float* __restrict__ b2,
                             const float* __restrict__ wfc,
                             const float* __restrict__ bfc,
                             float* __restrict__ y) {
    const int tid = threadIdx.x;          // 256
    const int r = tid >> 4, t = tid & 15;
    const int n = blockIdx.x * ANP + r;
    const float4* B4 = (const float4*)g_bufB;
    float disn = g_dis[n];
    float dd = __fmul_rn(disn, disn);
    float mx  = __uint_as_float(g_minmax[1]);
    float rng = __fsub_rn(mx, __uint_as_float(g_minmax[0]));

    int   s_t  = g_knn[n * KNN + t];
    float ew_t = __fdiv_rn(__fsub_rn(mx, g_d[n * KNN + t]), rng);
    float cf_t = __fmul_rn(__fmul_rn(g_dis[s_t], ew_t), disn);

    float4 a = B4[n * 16 + t];
    float4 acc;
    acc.x = __fmul_rn(dd, a.x); acc.y = __fmul_rn(dd, a.y);
    acc.z = __fmul_rn(dd, a.z); acc.w = __fmul_rn(dd, a.w);
#pragma unroll
    for (int k = 0; k < KNN; k++) {
        float coef = __shfl_sync(FULLM, cf_t, k, 16);
        int   s    = __shfl_sync(FULLM, s_t,  k, 16);
        float4 v = B4[s * 16 + t];
        acc.x = fmaf(coef, v.x, acc.x);
        acc.y = fmaf(coef, v.y, acc.y);
        acc.z = fmaf(coef, v.z, acc.z);
        acc.w = fmaf(coef, v.w, acc.w);
    }
    float4 bb = ((const float4*)b2)[t];
    float4 wv = ((const float4*)wfc)[t];
    float p = 0.0f;
    p = fmaf(fmaxf(__fadd_rn(acc.x, bb.x), 0.0f), wv.x, p);
    p = fmaf(fmaxf(__fadd_rn(acc.y, bb.y), 0.0f), wv.y, p);
    p = fmaf(fmaxf(__fadd_rn(acc.z, bb.z), 0.0f), wv.z, p);
    p = fmaf(fmaxf(__fadd_rn(acc.w, bb.w), 0.0f), wv.w, p);
#pragma unroll
    for (int off = 8; off > 0; off >>= 1)
        p += __shfl_down_sync(FULLM, p, off, 16);
    if (t == 0) y[n] = p + bfc[0];
}

// ---------------- launch -----------------------------------------------------
extern "C" void kernel_launch(void* const* d_in, const int* in_sizes, int n_in,
                              void* d_out, int out_size) {
    const float* x   = (const float*)d_in[0];
    const float* c   = (const float*)d_in[1];
    const float* W1  = (const float*)d_in[2];
    const float* b1  = (const float*)d_in[3];
    const float* W2  = (const float*)d_in[4];
    const float* b2  = (const float*)d_in[5];
    const float* Wfc = (const float*)d_in[6];
    const float* bfc = (const float*)d_in[7];
    float* y = (float*)d_out;

    prep_kernel<<<63, 256>>>(c);                   // 0
    fill_mm1_kernel<<<NBF + NN / 4, 256>>>(x, W1); // 1
    knn_edge_kernel<<<NN / QPB, 256>>>();          // 2 (5x5 + 9x9 + guard)
    deg_kernel<<<NN * KNN / 256, 256>>>();         // 3 (profiled)
    agg_mm2_kernel<<<NN / ANP, 256>>>(b1, W2);     // 4
    final_kernel<<<NN / ANP, 256>>>(b2, Wfc, bfc, y); // 5
}